// round 15
// baseline (speedup 1.0000x reference)
#include <cuda_runtime.h>
#include <cuda_bf16.h>
#include <cstdint>

// Problem constants
#define NN 50000
#define NE 800000
#define ET 850000
#define NG 64
#define FD 128
#define NCLS 10
#define NEG_SLOPE 0.2f
#define SCAN_B 512
#define SCAN_NB ((NN + SCAN_B - 1) / SCAN_B)
#define NEG_BIG -3.0e38f

// ------------------- device scratch -------------------
__device__ float g_xl[NN * FD];
__device__ float g_xr[NN * FD];
__device__ float g_h0[NN * FD];
__device__ float g_h1[NN * FD];
__device__ __nv_bfloat16 g_ahi[NN * FD];        // current layer's GEMM input, hi part
__device__ __nv_bfloat16 g_alo[NN * FD];        // lo part
__device__ __nv_bfloat16 g_wthi[6 * FD * FD];   // [layer*2+side][n][k]
__device__ __nv_bfloat16 g_wtlo[6 * FD * FD];
__device__ int   g_deg[NN];
__device__ int   g_excl[NN];
__device__ int   g_blk[SCAN_NB];
__device__ int   g_rowptr[NN + 1];
__device__ int   g_fill[NN];
__device__ int   g_src[ET];
__device__ float g_pool[NG * FD];
__device__ float g_cnt[NG];
__device__ int   g_is64;

__device__ __forceinline__ float eluf(float x) {
    return x > 0.0f ? x : (__expf(x) - 1.0f);
}

__device__ __forceinline__ int load_idx(const void* p, long long i, int is64) {
    if (is64) return (int)(((const long long*)p)[i]);
    return ((const int*)p)[i];
}

__device__ __forceinline__ uint32_t smem_u32(const void* p) {
    uint32_t a;
    asm("{ .reg .u64 t; cvta.to.shared.u64 t, %1; cvt.u32.u64 %0, t; }" : "=r"(a) : "l"(p));
    return a;
}

__device__ __forceinline__ void cpa16(uint32_t dst, const void* src, int sz) {
    asm volatile("cp.async.ca.shared.global [%0], [%1], 16, %2;"
                 :: "r"(dst), "l"(src), "r"(sz) : "memory");
}
#define CP_COMMIT() asm volatile("cp.async.commit_group;" ::: "memory")
#define CP_WAIT1()  asm volatile("cp.async.wait_group 1;" ::: "memory")
#define CP_WAIT0()  asm volatile("cp.async.wait_group 0;" ::: "memory")

// ------------------- dtype detection -------------------
__global__ void k_detect(const long long* __restrict__ ei) {
    if (threadIdx.x == 0 && blockIdx.x == 0) {
        int ok64 = 1;
        for (int i = 0; i < 64; i++) {
            long long v = ei[i];
            if (v < 0 || v >= (long long)NN) { ok64 = 0; break; }
        }
        g_is64 = ok64;
    }
}

// ------------------- CSR build -------------------
__global__ void k_init() {
    int i = blockIdx.x * blockDim.x + threadIdx.x;
    if (i < NN) { g_deg[i] = 1; g_fill[i] = 0; }
    if (i < NG * FD) g_pool[i] = 0.0f;
    if (i < NG) g_cnt[i] = 0.0f;
}

__global__ void k_hist(const void* __restrict__ ei) {
    int e = blockIdx.x * blockDim.x + threadIdx.x;
    if (e < NE) atomicAdd(&g_deg[load_idx(ei, (long long)NE + e, g_is64)], 1);
}

__global__ void k_scan1() {
    __shared__ int sm[SCAN_B];
    int i = blockIdx.x * SCAN_B + threadIdx.x;
    int v = (i < NN) ? g_deg[i] : 0;
    sm[threadIdx.x] = v;
    __syncthreads();
    for (int o = 1; o < SCAN_B; o <<= 1) {
        int t = (threadIdx.x >= o) ? sm[threadIdx.x - o] : 0;
        __syncthreads();
        sm[threadIdx.x] += t;
        __syncthreads();
    }
    if (i < NN) g_excl[i] = sm[threadIdx.x] - v;
    if (threadIdx.x == SCAN_B - 1) g_blk[blockIdx.x] = sm[SCAN_B - 1];
}

__global__ void k_scan2() {
    if (threadIdx.x == 0) {
        int run = 0;
        for (int b = 0; b < SCAN_NB; b++) { int t = g_blk[b]; g_blk[b] = run; run += t; }
        g_rowptr[NN] = ET;
    }
}

__global__ void k_scan3() {
    int i = blockIdx.x * SCAN_B + threadIdx.x;
    if (i < NN) g_rowptr[i] = g_excl[i] + g_blk[blockIdx.x];
}

__global__ void k_scatter(const void* __restrict__ ei) {
    int e = blockIdx.x * blockDim.x + threadIdx.x;
    if (e >= ET) return;
    int s, d;
    if (e < NE) {
        int is64 = g_is64;
        s = load_idx(ei, e, is64);
        d = load_idx(ei, (long long)NE + e, is64);
    } else {
        s = e - NE; d = e - NE;
    }
    int pos = g_rowptr[d] + atomicAdd(&g_fill[d], 1);
    g_src[pos] = s;
}

// ------------------- conversions -------------------
__global__ void k_convA0(const float* __restrict__ x) {
    int i = blockIdx.x * blockDim.x + threadIdx.x;
    if (i >= NN * FD) return;
    float a = x[i];
    __nv_bfloat16 h = __float2bfloat16(a);
    g_ahi[i] = h;
    g_alo[i] = __float2bfloat16(a - __bfloat162float(h));
}

__global__ void k_convW(const float* __restrict__ Wl, const float* __restrict__ Wr) {
    int i = blockIdx.x * blockDim.x + threadIdx.x;   // over 3*128*128
    if (i >= 3 * FD * FD) return;
    int l = i >> 14, r = i & 16383;
    int k = r >> 7, n = r & 127;
    float a = Wl[l * FD * FD + k * FD + n];
    __nv_bfloat16 ah = __float2bfloat16(a);
    g_wthi[(l * 2 + 0) * FD * FD + n * FD + k] = ah;
    g_wtlo[(l * 2 + 0) * FD * FD + n * FD + k] = __float2bfloat16(a - __bfloat162float(ah));
    float b = Wr[l * FD * FD + k * FD + n];
    __nv_bfloat16 bh = __float2bfloat16(b);
    g_wthi[(l * 2 + 1) * FD * FD + n * FD + k] = bh;
    g_wtlo[(l * 2 + 1) * FD * FD + n * FD + k] = __float2bfloat16(b - __bfloat162float(bh));
}

// ------------------- cp.async double-buffered mma.sync GEMM -------------------
#define KSTR 40
#define TILE_B 10240
#define BUF_B  (4 * TILE_B)
#define GSM_TOTAL (2 * BUF_B)

#define MMA_BF16(c, a, b0v, b1v) \
    asm volatile("mma.sync.aligned.m16n8k16.row.col.f32.bf16.bf16.f32 " \
        "{%0,%1,%2,%3}, {%4,%5,%6,%7}, {%8,%9}, {%0,%1,%2,%3};" \
        : "+f"((c)[0]), "+f"((c)[1]), "+f"((c)[2]), "+f"((c)[3]) \
        : "r"((a)[0]), "r"((a)[1]), "r"((a)[2]), "r"((a)[3]), "r"(b0v), "r"(b1v))

#define LDSM_X4(r, addr) \
    asm volatile("ldmatrix.sync.aligned.m8n8.x4.shared.b16 {%0,%1,%2,%3}, [%4];" \
        : "=r"((r)[0]), "=r"((r)[1]), "=r"((r)[2]), "=r"((r)[3]) : "r"(addr))

template<int SIDE, int WIDX>
__global__ void __launch_bounds__(256, 2) k_gemm_cp(const float* __restrict__ bias)
{
    extern __shared__ char dsm[];
    float* out = SIDE ? g_xr : g_xl;

    const int tid  = threadIdx.x;
    const int wid  = tid >> 5;
    const int lane = tid & 31;
    const int grp  = lane >> 2;
    const int tig  = lane & 3;
    const int mstrip = (wid & 3) * 32;
    const int nstrip = (wid >> 2) * 64;
    const int rowBase = blockIdx.x * 128;
    const uint32_t smB = smem_u32(dsm);

    auto issue_chunk = [&](int kb, int b) {
        const uint32_t base = smB + (uint32_t)b * BUF_B;
        const __nv_bfloat16* wh = &g_wthi[(size_t)WIDX * FD * FD];
        const __nv_bfloat16* wl = &g_wtlo[(size_t)WIDX * FD * FD];
#pragma unroll
        for (int i = 0; i < 2; i++) {
            int f = tid + i * 256;
            int r = f >> 2;
            int c16 = f & 3;
            uint32_t doff = (uint32_t)r * 80u + (uint32_t)c16 * 16u;
            size_t acol = (size_t)(kb * 32 + c16 * 8);
            int gr = rowBase + r;
            int sz = (gr < NN) ? 16 : 0;
            const char* asrch = (const char*)g_ahi + ((size_t)(gr < NN ? gr : 0) * FD + acol) * 2;
            const char* asrcl = (const char*)g_alo + ((size_t)(gr < NN ? gr : 0) * FD + acol) * 2;
            cpa16(base + doff,              asrch, sz);
            cpa16(base + TILE_B + doff,     asrcl, sz);
            cpa16(base + 2 * TILE_B + doff, (const char*)(wh + (size_t)r * FD) + acol * 2, 16);
            cpa16(base + 3 * TILE_B + doff, (const char*)(wl + (size_t)r * FD) + acol * 2, 16);
        }
    };

    const int i8 = lane & 7;
    const int g  = lane >> 3;
    uint32_t aOff[2], bOff[4];
#pragma unroll
    for (int mt = 0; mt < 2; mt++) {
        int arow = mstrip + mt * 16 + i8 + ((g & 1) << 3);
        int akof = (g >> 1) << 3;
        aOff[mt] = (uint32_t)(arow * KSTR + akof) * 2u;
    }
#pragma unroll
    for (int p = 0; p < 4; p++) {
        int nrow = nstrip + p * 16 + i8 + ((g >> 1) << 3);
        int bkof = (g & 1) << 3;
        bOff[p] = (uint32_t)(nrow * KSTR + bkof) * 2u;
    }

    float acc[2][8][4];
#pragma unroll
    for (int mt = 0; mt < 2; mt++)
#pragma unroll
        for (int nt = 0; nt < 8; nt++)
#pragma unroll
            for (int q = 0; q < 4; q++) acc[mt][nt][q] = 0.0f;

    issue_chunk(0, 0); CP_COMMIT();
    issue_chunk(1, 1); CP_COMMIT();

#pragma unroll
    for (int kb = 0; kb < 4; kb++) {
        if (kb < 3) { CP_WAIT1(); } else { CP_WAIT0(); }
        __syncthreads();

        const uint32_t bufB = smB + (uint32_t)(kb & 1) * BUF_B;
        const uint32_t aHiB = bufB;
        const uint32_t aLoB = bufB + TILE_B;
        const uint32_t wHiB = bufB + 2 * TILE_B;
        const uint32_t wLoB = bufB + 3 * TILE_B;

#pragma unroll
        for (int s = 0; s < 2; s++) {
            const uint32_t soff = (uint32_t)s * 32u;
            uint32_t ah[2][4], al[2][4];
#pragma unroll
            for (int mt = 0; mt < 2; mt++) {
                LDSM_X4(ah[mt], aHiB + aOff[mt] + soff);
                LDSM_X4(al[mt], aLoB + aOff[mt] + soff);
            }
#pragma unroll
            for (int p = 0; p < 4; p++) {
                uint32_t bh[4], bl[4];
                LDSM_X4(bh, wHiB + bOff[p] + soff);
                LDSM_X4(bl, wLoB + bOff[p] + soff);
                const int nt0 = 2 * p, nt1 = 2 * p + 1;
#pragma unroll
                for (int mt = 0; mt < 2; mt++) {
                    MMA_BF16(acc[mt][nt0], ah[mt], bh[0], bh[1]);
                    MMA_BF16(acc[mt][nt0], al[mt], bh[0], bh[1]);
                    MMA_BF16(acc[mt][nt0], ah[mt], bl[0], bl[1]);
                    MMA_BF16(acc[mt][nt1], ah[mt], bh[2], bh[3]);
                    MMA_BF16(acc[mt][nt1], al[mt], bh[2], bh[3]);
                    MMA_BF16(acc[mt][nt1], ah[mt], bl[2], bl[3]);
                }
            }
        }
        __syncthreads();
        if (kb + 2 < 4) { issue_chunk(kb + 2, kb & 1); CP_COMMIT(); }
    }

#pragma unroll
    for (int nt = 0; nt < 8; nt++) {
        int col = nstrip + nt * 8 + 2 * tig;
        float2 bv = *(const float2*)&bias[col];
#pragma unroll
        for (int mt = 0; mt < 2; mt++) {
            int r0 = rowBase + mstrip + mt * 16 + grp;
            if (r0 < NN) {
                float2 o0 = make_float2(acc[mt][nt][0] + bv.x, acc[mt][nt][1] + bv.y);
                *(float2*)&out[(size_t)r0 * FD + col] = o0;
            }
            if (r0 + 8 < NN) {
                float2 o1 = make_float2(acc[mt][nt][2] + bv.x, acc[mt][nt][3] + bv.y);
                *(float2*)&out[(size_t)(r0 + 8) * FD + col] = o1;
            }
        }
    }
}

// ------------------- fused edge aggregation: 2-stage pipelined gathers -------------------
// Pair-of-edges iterations. Indices prefetched 2 iters ahead, features 1 iter ahead,
// batch-max online-softmax update (exact math). Odd tail edge fully prefetched.
template<int OSEL, int POOL, int CONV>
__global__ void __launch_bounds__(128) k_aggr(const float* __restrict__ att,
                                              const float* __restrict__ bias,
                                              const void* __restrict__ batch)
{
    float* hout = (OSEL == 0) ? g_h0 : g_h1;
    int i   = blockIdx.x;
    int tid = threadIdx.x;

    float rx = g_xr[i * FD + tid];
    float at = att[tid];
    int beg = g_rowptr[i], end = g_rowptr[i + 1];
    int deg = end - beg;
    int npair = deg >> 1;
    int odd = deg & 1;

    // prefetch odd-tail edge (index + feature) up front — off the critical chain
    int st = 0; float vt = 0.0f;
    if (odd) {
        st = g_src[end - 1];
        vt = g_xl[st * FD + tid];
    }

    float m = NEG_BIG, den = 0.0f, acc = 0.0f;

    // pipeline registers: sB = indices for pair it+1, vA = features for pair it
    int sB0 = 0, sB1 = 0;
    float vA0 = 0.0f, vA1 = 0.0f;
    if (npair > 0) {
        int s0 = g_src[beg], s1 = g_src[beg + 1];
        if (npair > 1) { sB0 = g_src[beg + 2]; sB1 = g_src[beg + 3]; }
        vA0 = g_xl[s0 * FD + tid];
        vA1 = g_xl[s1 * FD + tid];
    }

    for (int it = 0; it < npair; it++) {
        float v0 = vA0, v1 = vA1;
        // prefetch indices for it+2
        int sC0 = 0, sC1 = 0;
        if (it + 2 < npair) {
            int eo = beg + 2 * (it + 2);
            sC0 = g_src[eo]; sC1 = g_src[eo + 1];
        }
        // prefetch features for it+1
        if (it + 1 < npair) {
            vA0 = g_xl[sB0 * FD + tid];
            vA1 = g_xl[sB1 * FD + tid];
        }

        float t0 = v0 + rx, t1 = v1 + rx;
        float p0 = (t0 > 0.0f ? t0 : NEG_SLOPE * t0) * at;
        float p1 = (t1 > 0.0f ? t1 : NEG_SLOPE * t1) * at;
#pragma unroll
        for (int o = 16; o; o >>= 1) {
            p0 += __shfl_xor_sync(0xffffffffu, p0, o);
            p1 += __shfl_xor_sync(0xffffffffu, p1, o);
        }
        // batch-max update (exact): one rescale, two parallel exps
        float nm = fmaxf(m, fmaxf(p0, p1));
        float f  = __expf(m - nm);
        float w0 = __expf(p0 - nm);
        float w1 = __expf(p1 - nm);
        den = den * f + w0 + w1;
        acc = acc * f + fmaf(w0, v0, w1 * v1);
        m = nm;

        sB0 = sC0; sB1 = sC1;
    }

    if (odd) {
        float t0 = vt + rx;
        float p0 = (t0 > 0.0f ? t0 : NEG_SLOPE * t0) * at;
#pragma unroll
        for (int o = 16; o; o >>= 1) p0 += __shfl_xor_sync(0xffffffffu, p0, o);
        float nm = fmaxf(m, p0);
        float f  = __expf(m - nm);
        float w  = __expf(p0 - nm);
        den = den * f + w;
        acc = acc * f + w * vt;
        m = nm;
    }

    float val = eluf(acc / den + bias[tid]);
    int idx = i * FD + tid;
    hout[idx] = val;
    if (CONV) {
        __nv_bfloat16 h = __float2bfloat16(val);
        g_ahi[idx] = h;
        g_alo[idx] = __float2bfloat16(val - __bfloat162float(h));
    }
    if (POOL) {
        int g = load_idx(batch, i, g_is64);
        atomicAdd(&g_pool[g * FD + tid], val);
        if (tid == 0) atomicAdd(&g_cnt[g], 1.0f);
    }
}

// ------------------- final head -------------------
__global__ void k_final(const float* __restrict__ lw, const float* __restrict__ lb,
                        float* __restrict__ out)
{
    __shared__ float sh[NCLS];
    int g = blockIdx.x;
    int j = threadIdx.x;
    if (j < NCLS) {
        float cnt = fmaxf(g_cnt[g], 1.0f);
        float s = lb[j];
        for (int f = 0; f < FD; f++)
            s += (g_pool[g * FD + f] / cnt) * lw[f * NCLS + j];
        sh[j] = eluf(s);
    }
    __syncthreads();
    if (j < NCLS) {
        float mx = NEG_BIG;
#pragma unroll
        for (int jj = 0; jj < NCLS; jj++) mx = fmaxf(mx, sh[jj]);
        float ls = 0.0f;
#pragma unroll
        for (int jj = 0; jj < NCLS; jj++) ls += __expf(sh[jj] - mx);
        out[g * NCLS + j] = sh[j] - mx - __logf(ls);
    }
}

// ------------------- launch -------------------
extern "C" void kernel_launch(void* const* d_in, const int* in_sizes, int n_in,
                              void* d_out, int out_size)
{
    const float* x    = (const float*)d_in[0];
    const void*  ei   = d_in[1];
    const void*  bat  = d_in[2];
    const float* Wl   = (const float*)d_in[3];
    const float* Wr   = (const float*)d_in[4];
    const float* bl   = (const float*)d_in[5];
    const float* br   = (const float*)d_in[6];
    const float* att  = (const float*)d_in[7];
    const float* bias = (const float*)d_in[8];
    const float* lw   = (const float*)d_in[9];
    const float* lb   = (const float*)d_in[10];
    float* out = (float*)d_out;

    cudaFuncSetAttribute(k_gemm_cp<0, 0>, cudaFuncAttributeMaxDynamicSharedMemorySize, GSM_TOTAL);
    cudaFuncSetAttribute(k_gemm_cp<1, 1>, cudaFuncAttributeMaxDynamicSharedMemorySize, GSM_TOTAL);
    cudaFuncSetAttribute(k_gemm_cp<0, 2>, cudaFuncAttributeMaxDynamicSharedMemorySize, GSM_TOTAL);
    cudaFuncSetAttribute(k_gemm_cp<1, 3>, cudaFuncAttributeMaxDynamicSharedMemorySize, GSM_TOTAL);
    cudaFuncSetAttribute(k_gemm_cp<0, 4>, cudaFuncAttributeMaxDynamicSharedMemorySize, GSM_TOTAL);
    cudaFuncSetAttribute(k_gemm_cp<1, 5>, cudaFuncAttributeMaxDynamicSharedMemorySize, GSM_TOTAL);

    const int gblocks = (NN + 127) / 128;   // 391

    k_detect<<<1, 32>>>((const long long*)ei);
    k_init<<<(NN + 255) / 256, 256>>>();
    k_convW<<<(3 * FD * FD + 255) / 256, 256>>>(Wl, Wr);
    k_convA0<<<(NN * FD + 255) / 256, 256>>>(x);
    k_gemm_cp<0, 0><<<gblocks, 256, GSM_TOTAL>>>(bl + 0 * FD);
    k_gemm_cp<1, 1><<<gblocks, 256, GSM_TOTAL>>>(br + 0 * FD);
    k_hist<<<(NE + 255) / 256, 256>>>(ei);
    k_scan1<<<SCAN_NB, SCAN_B>>>();
    k_scan2<<<1, 32>>>();
    k_scan3<<<SCAN_NB, SCAN_B>>>();
    k_scatter<<<(ET + 255) / 256, 256>>>(ei);
    k_aggr<0, 0, 1><<<NN, FD>>>(att + 0 * FD, bias + 0 * FD, bat);   // h0 + conv

    k_gemm_cp<0, 2><<<gblocks, 256, GSM_TOTAL>>>(bl + 1 * FD);
    k_gemm_cp<1, 3><<<gblocks, 256, GSM_TOTAL>>>(br + 1 * FD);
    k_aggr<1, 0, 1><<<NN, FD>>>(att + 1 * FD, bias + 1 * FD, bat);   // h1 + conv

    k_gemm_cp<0, 4><<<gblocks, 256, GSM_TOTAL>>>(bl + 2 * FD);
    k_gemm_cp<1, 5><<<gblocks, 256, GSM_TOTAL>>>(br + 2 * FD);
    k_aggr<0, 1, 0><<<NN, FD>>>(att + 2 * FD, bias + 2 * FD, bat);   // h0 + pool

    k_final<<<NG, 32>>>(lw, lb, out);
}

// round 16
// speedup vs baseline: 1.0815x; 1.0815x over previous
#include <cuda_runtime.h>
#include <cuda_bf16.h>
#include <cstdint>

// Problem constants
#define NN 50000
#define NE 800000
#define ET 850000
#define NG 64
#define FD 128
#define NCLS 10
#define NEG_SLOPE 0.2f
#define SCAN_B 512
#define SCAN_NB ((NN + SCAN_B - 1) / SCAN_B)
#define NEG_BIG -3.0e38f
#define GB 391                          // GEMM blocks per side

// ------------------- device scratch -------------------
__device__ float g_xl[NN * FD];
__device__ float g_xr[NN * FD];
__device__ float g_h0[NN * FD];
__device__ float g_h1[NN * FD];
__device__ __nv_bfloat16 g_ahi[NN * FD];        // current layer's GEMM input, hi part
__device__ __nv_bfloat16 g_alo[NN * FD];        // lo part
__device__ __nv_bfloat16 g_wthi[6 * FD * FD];   // [layer*2+side][n][k]
__device__ __nv_bfloat16 g_wtlo[6 * FD * FD];
__device__ int   g_deg[NN];
__device__ int   g_excl[NN];
__device__ int   g_blk[SCAN_NB];
__device__ int   g_rowptr[NN + 1];
__device__ int   g_fill[NN];
__device__ int   g_src[ET];
__device__ float g_pool[NG * FD];
__device__ float g_cnt[NG];
__device__ int   g_is64;

__device__ __forceinline__ float eluf(float x) {
    return x > 0.0f ? x : (__expf(x) - 1.0f);
}

__device__ __forceinline__ int load_idx(const void* p, long long i, int is64) {
    if (is64) return (int)(((const long long*)p)[i]);
    return ((const int*)p)[i];
}

__device__ __forceinline__ uint32_t smem_u32(const void* p) {
    uint32_t a;
    asm("{ .reg .u64 t; cvta.to.shared.u64 t, %1; cvt.u32.u64 %0, t; }" : "=r"(a) : "l"(p));
    return a;
}

__device__ __forceinline__ void cpa16(uint32_t dst, const void* src, int sz) {
    asm volatile("cp.async.ca.shared.global [%0], [%1], 16, %2;"
                 :: "r"(dst), "l"(src), "r"(sz) : "memory");
}
#define CP_COMMIT() asm volatile("cp.async.commit_group;" ::: "memory")
#define CP_WAIT1()  asm volatile("cp.async.wait_group 1;" ::: "memory")
#define CP_WAIT0()  asm volatile("cp.async.wait_group 0;" ::: "memory")

// ------------------- dtype detection -------------------
__global__ void k_detect(const long long* __restrict__ ei) {
    if (threadIdx.x == 0 && blockIdx.x == 0) {
        int ok64 = 1;
        for (int i = 0; i < 64; i++) {
            long long v = ei[i];
            if (v < 0 || v >= (long long)NN) { ok64 = 0; break; }
        }
        g_is64 = ok64;
    }
}

// ------------------- CSR build -------------------
__global__ void k_init() {
    int i = blockIdx.x * blockDim.x + threadIdx.x;
    if (i < NN) { g_deg[i] = 1; g_fill[i] = 0; }
    if (i < NG * FD) g_pool[i] = 0.0f;
    if (i < NG) g_cnt[i] = 0.0f;
}

__global__ void k_hist(const void* __restrict__ ei) {
    int e = blockIdx.x * blockDim.x + threadIdx.x;
    if (e < NE) atomicAdd(&g_deg[load_idx(ei, (long long)NE + e, g_is64)], 1);
}

__global__ void k_scan1() {
    __shared__ int sm[SCAN_B];
    int i = blockIdx.x * SCAN_B + threadIdx.x;
    int v = (i < NN) ? g_deg[i] : 0;
    sm[threadIdx.x] = v;
    __syncthreads();
    for (int o = 1; o < SCAN_B; o <<= 1) {
        int t = (threadIdx.x >= o) ? sm[threadIdx.x - o] : 0;
        __syncthreads();
        sm[threadIdx.x] += t;
        __syncthreads();
    }
    if (i < NN) g_excl[i] = sm[threadIdx.x] - v;
    if (threadIdx.x == SCAN_B - 1) g_blk[blockIdx.x] = sm[SCAN_B - 1];
}

__global__ void k_scan2() {
    if (threadIdx.x == 0) {
        int run = 0;
        for (int b = 0; b < SCAN_NB; b++) { int t = g_blk[b]; g_blk[b] = run; run += t; }
        g_rowptr[NN] = ET;
    }
}

__global__ void k_scan3() {
    int i = blockIdx.x * SCAN_B + threadIdx.x;
    if (i < NN) g_rowptr[i] = g_excl[i] + g_blk[blockIdx.x];
}

__global__ void k_scatter(const void* __restrict__ ei) {
    int e = blockIdx.x * blockDim.x + threadIdx.x;
    if (e >= ET) return;
    int s, d;
    if (e < NE) {
        int is64 = g_is64;
        s = load_idx(ei, e, is64);
        d = load_idx(ei, (long long)NE + e, is64);
    } else {
        s = e - NE; d = e - NE;
    }
    int pos = g_rowptr[d] + atomicAdd(&g_fill[d], 1);
    g_src[pos] = s;
}

// ------------------- conversions -------------------
__global__ void k_convA0(const float* __restrict__ x) {
    int i = blockIdx.x * blockDim.x + threadIdx.x;
    if (i >= NN * FD) return;
    float a = x[i];
    __nv_bfloat16 h = __float2bfloat16(a);
    g_ahi[i] = h;
    g_alo[i] = __float2bfloat16(a - __bfloat162float(h));
}

__global__ void k_convW(const float* __restrict__ Wl, const float* __restrict__ Wr) {
    int i = blockIdx.x * blockDim.x + threadIdx.x;   // over 3*128*128
    if (i >= 3 * FD * FD) return;
    int l = i >> 14, r = i & 16383;
    int k = r >> 7, n = r & 127;
    float a = Wl[l * FD * FD + k * FD + n];
    __nv_bfloat16 ah = __float2bfloat16(a);
    g_wthi[(l * 2 + 0) * FD * FD + n * FD + k] = ah;
    g_wtlo[(l * 2 + 0) * FD * FD + n * FD + k] = __float2bfloat16(a - __bfloat162float(ah));
    float b = Wr[l * FD * FD + k * FD + n];
    __nv_bfloat16 bh = __float2bfloat16(b);
    g_wthi[(l * 2 + 1) * FD * FD + n * FD + k] = bh;
    g_wtlo[(l * 2 + 1) * FD * FD + n * FD + k] = __float2bfloat16(b - __bfloat162float(bh));
}

// ------------------- merged dual-side cp.async GEMM -------------------
// One launch per layer: 782 blocks, side = blockIdx.x >= GB. Both outputs are
// __device__ globals (runtime select stays in .global space).
#define KSTR 40
#define TILE_B 10240
#define BUF_B  (4 * TILE_B)
#define GSM_TOTAL (2 * BUF_B)

#define MMA_BF16(c, a, b0v, b1v) \
    asm volatile("mma.sync.aligned.m16n8k16.row.col.f32.bf16.bf16.f32 " \
        "{%0,%1,%2,%3}, {%4,%5,%6,%7}, {%8,%9}, {%0,%1,%2,%3};" \
        : "+f"((c)[0]), "+f"((c)[1]), "+f"((c)[2]), "+f"((c)[3]) \
        : "r"((a)[0]), "r"((a)[1]), "r"((a)[2]), "r"((a)[3]), "r"(b0v), "r"(b1v))

#define LDSM_X4(r, addr) \
    asm volatile("ldmatrix.sync.aligned.m8n8.x4.shared.b16 {%0,%1,%2,%3}, [%4];" \
        : "=r"((r)[0]), "=r"((r)[1]), "=r"((r)[2]), "=r"((r)[3]) : "r"(addr))

template<int LAYER>
__global__ void __launch_bounds__(256, 2) k_gemm_cp(const float* __restrict__ bl,
                                                    const float* __restrict__ br)
{
    extern __shared__ char dsm[];
    const int side = (blockIdx.x >= GB) ? 1 : 0;
    const int blk  = blockIdx.x - side * GB;
    float* out = side ? g_xr : g_xl;
    const float* bias = side ? br : bl;
    const int widx = LAYER * 2 + side;

    const int tid  = threadIdx.x;
    const int wid  = tid >> 5;
    const int lane = tid & 31;
    const int grp  = lane >> 2;
    const int tig  = lane & 3;
    const int mstrip = (wid & 3) * 32;
    const int nstrip = (wid >> 2) * 64;
    const int rowBase = blk * 128;
    const uint32_t smB = smem_u32(dsm);

    auto issue_chunk = [&](int kb, int b) {
        const uint32_t base = smB + (uint32_t)b * BUF_B;
        const __nv_bfloat16* wh = &g_wthi[(size_t)widx * FD * FD];
        const __nv_bfloat16* wl = &g_wtlo[(size_t)widx * FD * FD];
#pragma unroll
        for (int i = 0; i < 2; i++) {
            int f = tid + i * 256;
            int r = f >> 2;
            int c16 = f & 3;
            uint32_t doff = (uint32_t)r * 80u + (uint32_t)c16 * 16u;
            size_t acol = (size_t)(kb * 32 + c16 * 8);
            int gr = rowBase + r;
            int sz = (gr < NN) ? 16 : 0;
            const char* asrch = (const char*)g_ahi + ((size_t)(gr < NN ? gr : 0) * FD + acol) * 2;
            const char* asrcl = (const char*)g_alo + ((size_t)(gr < NN ? gr : 0) * FD + acol) * 2;
            cpa16(base + doff,              asrch, sz);
            cpa16(base + TILE_B + doff,     asrcl, sz);
            cpa16(base + 2 * TILE_B + doff, (const char*)(wh + (size_t)r * FD) + acol * 2, 16);
            cpa16(base + 3 * TILE_B + doff, (const char*)(wl + (size_t)r * FD) + acol * 2, 16);
        }
    };

    const int i8 = lane & 7;
    const int g  = lane >> 3;
    uint32_t aOff[2], bOff[4];
#pragma unroll
    for (int mt = 0; mt < 2; mt++) {
        int arow = mstrip + mt * 16 + i8 + ((g & 1) << 3);
        int akof = (g >> 1) << 3;
        aOff[mt] = (uint32_t)(arow * KSTR + akof) * 2u;
    }
#pragma unroll
    for (int p = 0; p < 4; p++) {
        int nrow = nstrip + p * 16 + i8 + ((g >> 1) << 3);
        int bkof = (g & 1) << 3;
        bOff[p] = (uint32_t)(nrow * KSTR + bkof) * 2u;
    }

    float acc[2][8][4];
#pragma unroll
    for (int mt = 0; mt < 2; mt++)
#pragma unroll
        for (int nt = 0; nt < 8; nt++)
#pragma unroll
            for (int q = 0; q < 4; q++) acc[mt][nt][q] = 0.0f;

    issue_chunk(0, 0); CP_COMMIT();
    issue_chunk(1, 1); CP_COMMIT();

#pragma unroll
    for (int kb = 0; kb < 4; kb++) {
        if (kb < 3) { CP_WAIT1(); } else { CP_WAIT0(); }
        __syncthreads();

        const uint32_t bufB = smB + (uint32_t)(kb & 1) * BUF_B;
        const uint32_t aHiB = bufB;
        const uint32_t aLoB = bufB + TILE_B;
        const uint32_t wHiB = bufB + 2 * TILE_B;
        const uint32_t wLoB = bufB + 3 * TILE_B;

#pragma unroll
        for (int s = 0; s < 2; s++) {
            const uint32_t soff = (uint32_t)s * 32u;
            uint32_t ah[2][4], al[2][4];
#pragma unroll
            for (int mt = 0; mt < 2; mt++) {
                LDSM_X4(ah[mt], aHiB + aOff[mt] + soff);
                LDSM_X4(al[mt], aLoB + aOff[mt] + soff);
            }
#pragma unroll
            for (int p = 0; p < 4; p++) {
                uint32_t bh[4], bl2[4];
                LDSM_X4(bh,  wHiB + bOff[p] + soff);
                LDSM_X4(bl2, wLoB + bOff[p] + soff);
                const int nt0 = 2 * p, nt1 = 2 * p + 1;
#pragma unroll
                for (int mt = 0; mt < 2; mt++) {
                    MMA_BF16(acc[mt][nt0], ah[mt], bh[0], bh[1]);
                    MMA_BF16(acc[mt][nt0], al[mt], bh[0], bh[1]);
                    MMA_BF16(acc[mt][nt0], ah[mt], bl2[0], bl2[1]);
                    MMA_BF16(acc[mt][nt1], ah[mt], bh[2], bh[3]);
                    MMA_BF16(acc[mt][nt1], al[mt], bh[2], bh[3]);
                    MMA_BF16(acc[mt][nt1], ah[mt], bl2[2], bl2[3]);
                }
            }
        }
        __syncthreads();
        if (kb + 2 < 4) { issue_chunk(kb + 2, kb & 1); CP_COMMIT(); }
    }

#pragma unroll
    for (int nt = 0; nt < 8; nt++) {
        int col = nstrip + nt * 8 + 2 * tig;
        float2 bv = *(const float2*)&bias[col];
#pragma unroll
        for (int mt = 0; mt < 2; mt++) {
            int r0 = rowBase + mstrip + mt * 16 + grp;
            if (r0 < NN) {
                float2 o0 = make_float2(acc[mt][nt][0] + bv.x, acc[mt][nt][1] + bv.y);
                *(float2*)&out[(size_t)r0 * FD + col] = o0;
            }
            if (r0 + 8 < NN) {
                float2 o1 = make_float2(acc[mt][nt][2] + bv.x, acc[mt][nt][3] + bv.y);
                *(float2*)&out[(size_t)(r0 + 8) * FD + col] = o1;
            }
        }
    }
}

// ------------------- fused edge aggregation (R14-proven simple EB2) -------------------
template<int OSEL, int POOL, int CONV>
__global__ void __launch_bounds__(128) k_aggr(const float* __restrict__ att,
                                              const float* __restrict__ bias,
                                              const void* __restrict__ batch)
{
    float* hout = (OSEL == 0) ? g_h0 : g_h1;
    int i   = blockIdx.x;
    int tid = threadIdx.x;

    float rx = g_xr[i * FD + tid];
    float at = att[tid];
    int beg = g_rowptr[i], end = g_rowptr[i + 1];

    float m = NEG_BIG, den = 0.0f, acc = 0.0f;
    int e = beg;

    if ((end - beg) & 1) {
        int s0 = g_src[e];
        float v0 = g_xl[s0 * FD + tid];
        float t0 = v0 + rx;
        float p0 = (t0 > 0.0f ? t0 : NEG_SLOPE * t0) * at;
#pragma unroll
        for (int o = 16; o; o >>= 1) p0 += __shfl_xor_sync(0xffffffffu, p0, o);
        float nm = fmaxf(m, p0);
        float f  = __expf(m - nm);
        float w  = __expf(p0 - nm);
        den = den * f + w;
        acc = acc * f + w * v0;
        m = nm;
        e++;
    }

    for (; e < end; e += 2) {
        int s0 = g_src[e], s1 = g_src[e + 1];
        float v0 = g_xl[s0 * FD + tid];
        float v1 = g_xl[s1 * FD + tid];
        float t0 = v0 + rx, t1 = v1 + rx;
        float p0 = (t0 > 0.0f ? t0 : NEG_SLOPE * t0) * at;
        float p1 = (t1 > 0.0f ? t1 : NEG_SLOPE * t1) * at;
#pragma unroll
        for (int o = 16; o; o >>= 1) {
            p0 += __shfl_xor_sync(0xffffffffu, p0, o);
            p1 += __shfl_xor_sync(0xffffffffu, p1, o);
        }
        float nm0 = fmaxf(m, p0);
        float f0  = __expf(m - nm0);
        float w0  = __expf(p0 - nm0);
        den = den * f0 + w0;
        acc = acc * f0 + w0 * v0;
        float nm1 = fmaxf(nm0, p1);
        float f1  = __expf(nm0 - nm1);
        float w1  = __expf(p1 - nm1);
        den = den * f1 + w1;
        acc = acc * f1 + w1 * v1;
        m = nm1;
    }

    float val = eluf(acc / den + bias[tid]);
    int idx = i * FD + tid;
    hout[idx] = val;
    if (CONV) {
        __nv_bfloat16 h = __float2bfloat16(val);
        g_ahi[idx] = h;
        g_alo[idx] = __float2bfloat16(val - __bfloat162float(h));
    }
    if (POOL) {
        int g = load_idx(batch, i, g_is64);
        atomicAdd(&g_pool[g * FD + tid], val);
        if (tid == 0) atomicAdd(&g_cnt[g], 1.0f);
    }
}

// ------------------- final head -------------------
__global__ void k_final(const float* __restrict__ lw, const float* __restrict__ lb,
                        float* __restrict__ out)
{
    __shared__ float sh[NCLS];
    int g = blockIdx.x;
    int j = threadIdx.x;
    if (j < NCLS) {
        float cnt = fmaxf(g_cnt[g], 1.0f);
        float s = lb[j];
        for (int f = 0; f < FD; f++)
            s += (g_pool[g * FD + f] / cnt) * lw[f * NCLS + j];
        sh[j] = eluf(s);
    }
    __syncthreads();
    if (j < NCLS) {
        float mx = NEG_BIG;
#pragma unroll
        for (int jj = 0; jj < NCLS; jj++) mx = fmaxf(mx, sh[jj]);
        float ls = 0.0f;
#pragma unroll
        for (int jj = 0; jj < NCLS; jj++) ls += __expf(sh[jj] - mx);
        out[g * NCLS + j] = sh[j] - mx - __logf(ls);
    }
}

// ------------------- launch -------------------
extern "C" void kernel_launch(void* const* d_in, const int* in_sizes, int n_in,
                              void* d_out, int out_size)
{
    const float* x    = (const float*)d_in[0];
    const void*  ei   = d_in[1];
    const void*  bat  = d_in[2];
    const float* Wl   = (const float*)d_in[3];
    const float* Wr   = (const float*)d_in[4];
    const float* bl   = (const float*)d_in[5];
    const float* br   = (const float*)d_in[6];
    const float* att  = (const float*)d_in[7];
    const float* bias = (const float*)d_in[8];
    const float* lw   = (const float*)d_in[9];
    const float* lb   = (const float*)d_in[10];
    float* out = (float*)d_out;

    cudaFuncSetAttribute(k_gemm_cp<0>, cudaFuncAttributeMaxDynamicSharedMemorySize, GSM_TOTAL);
    cudaFuncSetAttribute(k_gemm_cp<1>, cudaFuncAttributeMaxDynamicSharedMemorySize, GSM_TOTAL);
    cudaFuncSetAttribute(k_gemm_cp<2>, cudaFuncAttributeMaxDynamicSharedMemorySize, GSM_TOTAL);

    k_detect<<<1, 32>>>((const long long*)ei);
    k_init<<<(NN + 255) / 256, 256>>>();
    k_convW<<<(3 * FD * FD + 255) / 256, 256>>>(Wl, Wr);
    k_convA0<<<(NN * FD + 255) / 256, 256>>>(x);
    k_gemm_cp<0><<<2 * GB, 256, GSM_TOTAL>>>(bl + 0 * FD, br + 0 * FD);
    k_hist<<<(NE + 255) / 256, 256>>>(ei);
    k_scan1<<<SCAN_NB, SCAN_B>>>();
    k_scan2<<<1, 32>>>();
    k_scan3<<<SCAN_NB, SCAN_B>>>();
    k_scatter<<<(ET + 255) / 256, 256>>>(ei);
    k_aggr<0, 0, 1><<<NN, FD>>>(att + 0 * FD, bias + 0 * FD, bat);   // h0 + conv

    k_gemm_cp<1><<<2 * GB, 256, GSM_TOTAL>>>(bl + 1 * FD, br + 1 * FD);
    k_aggr<1, 0, 1><<<NN, FD>>>(att + 1 * FD, bias + 1 * FD, bat);   // h1 + conv

    k_gemm_cp<2><<<2 * GB, 256, GSM_TOTAL>>>(bl + 2 * FD, br + 2 * FD);
    k_aggr<0, 1, 0><<<NN, FD>>>(att + 2 * FD, bias + 2 * FD, bat);   // h0 + pool

    k_final<<<NG, 32>>>(lw, lb, out);
}